// round 8
// baseline (speedup 1.0000x reference)
#include <cuda_runtime.h>
#include <stdint.h>

#define BB   4
#define NN   1024
#define CC   80
#define KPC  100
#define MAXT 300
#define NEGV (-1e30f)
#define STHR 0.001f
#define CHNK 256     // alive candidates resolved per round
#define FSEL 512     // k_final selection cap
#define INVK 0xFFFFFFFFu

// ---------------- scratch ----------------
__device__ uint32_t g_mask[BB * NN * 32];
__device__ float    g_stage_s[BB * CC * KPC];
__device__ int      g_stage_b[BB * CC * KPC];

__device__ __forceinline__ uint32_t dbits(float f) {
    uint32_t u = __float_as_uint(f);
    return (u & 0x80000000u) ? u : (u ^ 0x7fffffffu);
}
__device__ __forceinline__ float undbits_pos(uint32_t d) {
    return __uint_as_float(d ^ 0x7fffffffu);   // valid for positive originals
}

// ---------------- K1: pairwise IoU>0.5 bitmask (fine-grained, 16-bit stores) ----------------
__global__ void __launch_bounds__(256) k_mask(const float4* __restrict__ boxes) {
    __shared__ float4 sj[256]; __shared__ float aj[256];
    __shared__ float4 si[16];  __shared__ float ai[16];
    const int b  = blockIdx.y;
    const int rt = blockIdx.x >> 2;
    const int ct = blockIdx.x & 3;
    const int tid = threadIdx.x;

    {
        float4 v = boxes[b * NN + ct * 256 + tid];
        float y1 = fminf(v.x, v.z), y2 = fmaxf(v.x, v.z);
        float x1 = fminf(v.y, v.w), x2 = fmaxf(v.y, v.w);
        sj[tid] = make_float4(y1, x1, y2, x2);
        aj[tid] = (y2 - y1) * (x2 - x1);
    }
    if (tid < 16) {
        float4 v = boxes[b * NN + rt * 16 + tid];
        float y1 = fminf(v.x, v.z), y2 = fmaxf(v.x, v.z);
        float x1 = fminf(v.y, v.w), x2 = fmaxf(v.y, v.w);
        si[tid] = make_float4(y1, x1, y2, x2);
        ai[tid] = (y2 - y1) * (x2 - x1);
    }
    __syncthreads();

    const int r    = tid >> 4;
    const int hw   = tid & 15;
    const int lane = tid & 31;
    float4 A = si[r];
    float  a = ai[r];
    uint32_t bits = 0;

    #pragma unroll
    for (int t = 0; t < 16; t++) {
        int c  = (t + lane) & 15;
        int jl = hw * 16 + c;
        float4 Bx = sj[jl];
        float  ab = aj[jl];
        float ih    = fmaxf(fminf(A.z, Bx.z) - fmaxf(A.x, Bx.x), 0.0f);
        float iw2   = fmaxf(fminf(A.w, Bx.w) - fmaxf(A.y, Bx.y), 0.0f);
        float inter = ih * iw2;
        float uni   = fmaxf(a + ab - inter, 1e-12f);
        if ((inter + inter) - uni > uni * 0x1p-24f) bits |= (1u << c);
    }
    uint16_t* gm16 = reinterpret_cast<uint16_t*>(g_mask);
    gm16[(size_t)(b * NN + rt * 16 + r) * 64 + ct * 16 + hw] = (uint16_t)bits;
}

// ---------------- K2: sort-1024 + alive-filtered rounds + ballot greedy ----------------
__global__ void __launch_bounds__(512) k_nms(const float* __restrict__ scores) {
    __shared__ uint32_t chkey[NN];                    // 4KB sorted keys
    __shared__ uint16_t chidx[NN];                    // 2KB box indices
    __shared__ uint32_t ckey2[CHNK];                  // round chunk (alive only)
    __shared__ uint16_t cidx2[CHNK];
    __shared__ alignas(16) uint32_t rows[CHNK * 32];  // 32KB mask rows
    __shared__ uint32_t sup_sh[32];
    __shared__ float    kept_s[KPC];
    __shared__ int      kept_i[KPC];
    __shared__ int      wcnt0[16], wcnt1[16];
    __shared__ int      s_kc, s_cur;

    const int c    = blockIdx.x;
    const int b    = blockIdx.y;
    const int tid  = threadIdx.x;
    const int wid  = tid >> 5;
    const int lane = tid & 31;
    const uint32_t lowm = (lane == 0) ? 0u : (0xffffffffu >> (32 - lane));

    if (tid < 32) sup_sh[tid] = 0;
    if (tid == 0) { s_kc = 0; s_cur = 0; }

    // load scores, build (key, idx)
    {
        float sA = scores[(b * NN + tid) * CC + c];
        float sB = scores[(b * NN + tid + 512) * CC + c];
        chkey[tid]       = (sA > STHR) ? dbits(sA) : INVK;
        chkey[tid + 512] = (sB > STHR) ? dbits(sB) : INVK;
        chidx[tid]       = (uint16_t)tid;
        chidx[tid + 512] = (uint16_t)(tid + 512);
    }
    __syncthreads();

    // hybrid bitonic sort of 1024 (key,idx) ascending; 2 elems/thread
    uint32_t k0 = chkey[tid],       i0 = chidx[tid];
    uint32_t k1 = chkey[tid + 512], i1 = chidx[tid + 512];
    for (int k2 = 2; k2 <= NN; k2 <<= 1) {
        for (int j = k2 >> 1; j > 0; j >>= 1) {
            if (j >= 32) {
                chkey[tid] = k0; chidx[tid] = (uint16_t)i0;
                chkey[tid + 512] = k1; chidx[tid + 512] = (uint16_t)i1;
                __syncthreads();
                int e = ((tid & ~(j - 1)) << 1) | (tid & (j - 1));
                int p = e | j;
                bool up = ((e & k2) == 0);
                uint32_t ka = chkey[e], kb = chkey[p];
                uint32_t ia = chidx[e], ib = chidx[p];
                bool agb = (ka > kb) || (ka == kb && ia > ib);
                if (agb == up) {
                    chkey[e] = kb; chkey[p] = ka;
                    chidx[e] = (uint16_t)ib; chidx[p] = (uint16_t)ia;
                }
                __syncthreads();
                k0 = chkey[tid];       i0 = chidx[tid];
                k1 = chkey[tid + 512]; i1 = chidx[tid + 512];
            } else {
                {
                    uint32_t pk = __shfl_xor_sync(0xffffffffu, k0, j);
                    uint32_t pi = __shfl_xor_sync(0xffffffffu, i0, j);
                    bool up = ((tid & k2) == 0);
                    bool keep_min = (((tid & j) == 0) == up);
                    bool plt = (pk < k0) || (pk == k0 && pi < i0);
                    if (keep_min == plt) { k0 = pk; i0 = pi; }
                }
                {
                    uint32_t pk = __shfl_xor_sync(0xffffffffu, k1, j);
                    uint32_t pi = __shfl_xor_sync(0xffffffffu, i1, j);
                    bool up = (((tid + 512) & k2) == 0);
                    bool keep_min = (((tid & j) == 0) == up);
                    bool plt = (pk < k1) || (pk == k1 && pi < i1);
                    if (keep_min == plt) { k1 = pk; i1 = pi; }
                }
            }
        }
    }
    chkey[tid] = k0; chidx[tid] = (uint16_t)i0;
    chkey[tid + 512] = k1; chidx[tid + 512] = (uint16_t)i1;
    __syncthreads();

    const uint4* gm4 = reinterpret_cast<const uint4*>(g_mask);
    uint4* bf4 = reinterpret_cast<uint4*>(rows);
    uint32_t sup = 0;     // warp0 registers, lane w = word w
    int kc = 0;           // warp0

    for (int round = 0; round < 6; round++) {
        // ---- compact first CHNK alive candidates in sorted order ----
        const int cur = s_cur;
        bool a0, a1;
        {
            uint32_t kk0 = chkey[tid], kk1 = chkey[tid + 512];
            uint16_t o0 = chidx[tid],  o1 = chidx[tid + 512];
            a0 = (tid >= cur)       && (kk0 != INVK) && !((sup_sh[o0 >> 5] >> (o0 & 31)) & 1u);
            a1 = (tid + 512 >= cur) && (kk1 != INVK) && !((sup_sh[o1 >> 5] >> (o1 & 31)) & 1u);
        }
        uint32_t b0 = __ballot_sync(0xffffffffu, a0);
        uint32_t b1 = __ballot_sync(0xffffffffu, a1);
        if (lane == 0) { wcnt0[wid] = __popc(b0); wcnt1[wid] = __popc(b1); }
        __syncthreads();
        int base0 = 0, base1 = 0, total0 = 0, total1 = 0;
        #pragma unroll
        for (int w = 0; w < 16; w++) {
            int c0 = wcnt0[w], c1 = wcnt1[w];
            if (w < wid) { base0 += c0; base1 += c1; }
            total0 += c0; total1 += c1;
        }
        const int total = total0 + total1;
        int rank0 = base0 + __popc(b0 & lowm);
        int rank1 = total0 + base1 + __popc(b1 & lowm);
        if (a0 && rank0 < CHNK) { ckey2[rank0] = chkey[tid]; cidx2[rank0] = chidx[tid]; }
        if (a1 && rank1 < CHNK) { ckey2[rank1] = chkey[tid + 512]; cidx2[rank1] = chidx[tid + 512]; }
        if (a0 && rank0 == CHNK - 1) s_cur = tid + 1;
        if (a1 && rank1 == CHNK - 1) s_cur = tid + 512 + 1;
        const int P = min(total, CHNK);
        __syncthreads();
        if (P == 0) break;

        // ---- preload rows for the P alive candidates ----
        for (int l = tid; l < P * 8; l += 512) {
            int r = l >> 3, q = l & 7;
            int o = (int)cidx2[r];
            bf4[(r << 3) | q] = gm4[(b * NN + o) * 8 + q];
        }
        __syncthreads();

        // ---- warp0: ballot greedy over P, barrier-free ----
        if (tid < 32) {
            for (int g0 = 0; g0 < P && kc < KPC; g0 += 32) {
                int gcnt = min(32, P - g0);
                bool has = (lane < gcnt);
                uint32_t o = 0, keyv = 0;
                if (has) { o = cidx2[g0 + lane]; keyv = ckey2[g0 + lane]; }
                uint32_t wl2 = o >> 5, bl = o & 31;

                uint32_t wsup = __shfl_sync(0xffffffffu, sup, (int)wl2);
                bool alive0 = has && !((wsup >> bl) & 1u);

                uint32_t colbits = 0;
                for (int m = 0; m < gcnt; m++) {
                    uint32_t rm = rows[((g0 + m) << 5) + wl2];
                    colbits |= ((rm >> bl) & 1u) << m;
                }

                uint32_t alive_mask = __ballot_sync(0xffffffffu, alive0);
                #pragma unroll 4
                for (int it = 0; it < 32; it++) {
                    bool a2 = alive0 && ((alive_mask & colbits & lowm) == 0);
                    uint32_t nm = __ballot_sync(0xffffffffu, a2);
                    if (nm == alive_mask) break;
                    alive_mask = nm;
                }

                int navail = KPC - kc;
                int myrank = __popc(alive_mask & lowm);
                bool keepme = ((alive_mask >> lane) & 1u) && (myrank < navail);
                uint32_t kept_mask = __ballot_sync(0xffffffffu, keepme);
                if (keepme) {
                    kept_i[kc + myrank] = (int)o;
                    kept_s[kc + myrank] = undbits_pos(keyv);
                }
                uint32_t km = kept_mask;
                while (km) {
                    int m = __ffs(km) - 1; km &= km - 1;
                    sup |= rows[((g0 + m) << 5) + lane];
                }
                kc += __popc(kept_mask);
            }
            sup_sh[lane] = sup;
            if (lane == 0) s_kc = kc;
        }
        __syncthreads();
        if (s_kc >= KPC || total <= CHNK) break;   // chunk resolved all remaining alive
    }
    __syncthreads();

    const int kcf = s_kc;
    if (tid < KPC) {
        int slot = (b * CC + c) * KPC + tid;
        if (tid < kcf) { g_stage_s[slot] = kept_s[tid]; g_stage_b[slot] = kept_i[tid]; }
        else           { g_stage_s[slot] = NEGV;        g_stage_b[slot] = 0; }
    }
}

// ---------------- K3: per-image top-300 of 8000 + output ----------------
__global__ void __launch_bounds__(1024) k_final(const float* __restrict__ boxes,
                                                float* __restrict__ out) {
    __shared__ uint32_t hist[4097];
    __shared__ uint32_t fkey[FSEL];
    __shared__ uint16_t fidx[FSEL];
    __shared__ uint32_t wsum[32];
    __shared__ int      s_cnt, s_bsel, s_total, s_m;

    const int b   = blockIdx.x;
    const int tid = threadIdx.x;
    const int M   = CC * KPC;
    const uint32_t BASE13 = 0x203FF;

    #pragma unroll
    for (int k = 0; k < 4; k++) hist[tid * 4 + k] = 0;
    if (tid == 0) { hist[4096] = 0; s_cnt = 0; s_bsel = 0; }

    float vals[8]; int idxs[8]; uint32_t keyb[8]; uint32_t binb[8]; bool valb[8];
    #pragma unroll
    for (int k = 0; k < 8; k++) {
        int f = tid + k * 1024;
        float s = (f < M) ? g_stage_s[b * M + f] : NEGV;
        vals[k] = s; idxs[k] = (f < M) ? f : 0;
        valb[k] = (s > NEGV * 0.5f);
        keyb[k] = dbits(s);
        int raw = (int)(keyb[k] >> 13) - (int)BASE13;
        binb[k] = (uint32_t)min(max(raw, 0), 4095);
    }
    __syncthreads();
    #pragma unroll
    for (int k = 0; k < 8; k++) if (valb[k]) atomicAdd(&hist[binb[k]], 1u);
    __syncthreads();

    uint32_t h[4];
    #pragma unroll
    for (int k = 0; k < 4; k++) h[k] = hist[4 * tid + k];
    uint32_t s4 = h[0] + h[1] + h[2] + h[3];
    uint32_t inc = s4;
    #pragma unroll
    for (int o = 1; o < 32; o <<= 1) {
        uint32_t v = __shfl_up_sync(0xffffffffu, inc, o);
        if ((tid & 31) >= o) inc += v;
    }
    if ((tid & 31) == 31) wsum[tid >> 5] = inc;
    __syncthreads();
    if (tid < 32) {
        uint32_t v = wsum[tid], in2 = v;
        #pragma unroll
        for (int o = 1; o < 32; o <<= 1) {
            uint32_t x = __shfl_up_sync(0xffffffffu, in2, o);
            if (tid >= o) in2 += x;
        }
        wsum[tid] = in2 - v;
    }
    __syncthreads();
    uint32_t excl = wsum[tid >> 5] + (inc - s4);
    uint32_t cum1 = excl + h[0], cum2 = cum1 + h[1], cum3 = cum2 + h[2], cum4 = excl + s4;
    hist[4 * tid] = excl; hist[4 * tid + 1] = cum1; hist[4 * tid + 2] = cum2; hist[4 * tid + 3] = cum3;
    if (tid == 1023) hist[4096] = cum4;
    if (cum1 <= (uint32_t)FSEL) atomicMax(&s_bsel, 4 * tid + 1);
    if (cum2 <= (uint32_t)FSEL) atomicMax(&s_bsel, 4 * tid + 2);
    if (cum3 <= (uint32_t)FSEL) atomicMax(&s_bsel, 4 * tid + 3);
    if (cum4 <= (uint32_t)FSEL) atomicMax(&s_bsel, 4 * tid + 4);
    __syncthreads();

    const int Bsel  = s_bsel;
    int P           = (int)hist[Bsel];
    const int total = (int)hist[4096];

    if (P >= MAXT || P >= total) {
        #pragma unroll
        for (int k = 0; k < 8; k++) {
            if (valb[k] && binb[k] < (uint32_t)Bsel) {
                int pos = atomicAdd(&s_cnt, 1);
                if (pos < FSEL) { fkey[pos] = keyb[k]; fidx[pos] = (uint16_t)idxs[k]; }
            }
        }
        if (tid == 0) s_m = P;
    } else {
        float lo = 0.0f, hi2 = 1.0f;
        for (int it = 0; it < 30; it++) {
            float mid = 0.5f * (lo + hi2);
            int cnt = 0;
            #pragma unroll
            for (int k = 0; k < 8; k++) cnt += (vals[k] > mid);
            #pragma unroll
            for (int o = 16; o; o >>= 1) cnt += __shfl_down_sync(0xffffffffu, cnt, o);
            if ((tid & 31) == 0) wsum[tid >> 5] = (uint32_t)cnt;
            __syncthreads();
            if (tid == 0) {
                int tot = 0;
                #pragma unroll
                for (int w2 = 0; w2 < 32; w2++) tot += (int)wsum[w2];
                s_total = tot;
            }
            __syncthreads();
            if (s_total >= MAXT) lo = mid; else hi2 = mid;
            __syncthreads();
        }
        if (tid == 0) s_cnt = 0;
        __syncthreads();
        #pragma unroll
        for (int k = 0; k < 8; k++) {
            if (vals[k] > lo) {
                int pos = atomicAdd(&s_cnt, 1);
                if (pos < FSEL) { fkey[pos] = dbits(vals[k]); fidx[pos] = (uint16_t)idxs[k]; }
            }
        }
        __syncthreads();
        if (tid == 0) s_m = min(s_cnt, FSEL);
    }
    __syncthreads();
    const int m = s_m;
    if (tid < FSEL && tid >= m) { fkey[tid] = 0xFFFFFFFFu; fidx[tid] = 0xFFFF; }
    __syncthreads();

    {
        uint32_t mk = 0xFFFFFFFFu, mi = 0xFFFFu;
        if (tid < FSEL) { mk = fkey[tid]; mi = fidx[tid]; }
        for (int k2 = 2; k2 <= FSEL; k2 <<= 1) {
            for (int j = k2 >> 1; j > 0; j >>= 1) {
                if (j >= 32) {
                    __syncthreads();
                    if (tid < FSEL) { fkey[tid] = mk; fidx[tid] = (uint16_t)mi; }
                    __syncthreads();
                    if (tid < FSEL) {
                        int p2 = tid ^ j;
                        uint32_t pk = fkey[p2], pi = fidx[p2];
                        bool up = ((tid & k2) == 0);
                        bool keep_min = (((tid & j) == 0) == up);
                        bool plt = (pk < mk) || (pk == mk && pi < mi);
                        if (keep_min == plt) { mk = pk; mi = pi; }
                    }
                } else if (tid < FSEL) {
                    uint32_t pk = __shfl_xor_sync(0xffffffffu, mk, j);
                    uint32_t pi = __shfl_xor_sync(0xffffffffu, mi, j);
                    bool up = ((tid & k2) == 0);
                    bool keep_min = (((tid & j) == 0) == up);
                    bool plt = (pk < mk) || (pk == mk && pi < mi);
                    if (keep_min == plt) { mk = pk; mi = pi; }
                }
            }
        }
        __syncthreads();
        if (tid < FSEL) { fkey[tid] = mk; fidx[tid] = (uint16_t)mi; }
        __syncthreads();
    }

    if (tid < MAXT) {
        bool valid = (tid < m);
        float sc = 0.0f, cls = 0.0f, bx0 = 0.0f, bx1 = 0.0f, bx2 = 0.0f, bx3 = 0.0f;
        if (valid) {
            int f = (int)fidx[tid];
            sc  = g_stage_s[b * M + f];
            cls = (float)(f / KPC);
            int bidx = g_stage_b[b * M + f];
            float4 bv = reinterpret_cast<const float4*>(boxes)[b * NN + bidx];
            bx0 = fminf(fmaxf(bv.x, 0.0f), 1.0f);
            bx1 = fminf(fmaxf(bv.y, 0.0f), 1.0f);
            bx2 = fminf(fmaxf(bv.z, 0.0f), 1.0f);
            bx3 = fminf(fmaxf(bv.w, 0.0f), 1.0f);
        }
        out[b * MAXT + tid] = sc;
        float* ob = out + BB * MAXT + (b * MAXT + tid) * 4;
        ob[0] = bx0; ob[1] = bx1; ob[2] = bx2; ob[3] = bx3;
        out[BB * MAXT * 5 + b * MAXT + tid] = cls;
    }
    if (tid == 0) out[BB * MAXT * 6 + b] = (float)min(m, MAXT);
}

// ---------------- launch ----------------
extern "C" void kernel_launch(void* const* d_in, const int* in_sizes, int n_in,
                              void* d_out, int out_size) {
    const float* scores = (const float*)d_in[0];   // [4,1024,80] f32
    const float* boxes  = (const float*)d_in[1];   // [4,1024,1,4] f32
    float* out = (float*)d_out;

    k_mask<<<dim3(256, BB), 256>>>((const float4*)boxes);
    k_nms<<<dim3(CC, BB), 512>>>(scores);
    k_final<<<BB, 1024>>>(boxes, out);
}

// round 9
// speedup vs baseline: 1.5295x; 1.5295x over previous
#include <cuda_runtime.h>
#include <stdint.h>

#define BB   4
#define NN   1024
#define CC   80
#define KPC  100
#define MAXT 300
#define NEGV (-1e30f)
#define STHR 0.001f
#define CHNK 256     // k_nms chunk capacity
#define FSEL 512     // k_final selection cap

// ---------------- scratch ----------------
__device__ uint32_t g_mask[BB * NN * 32];
__device__ float    g_stage_s[BB * CC * KPC];
__device__ int      g_stage_b[BB * CC * KPC];

__device__ __forceinline__ uint32_t dbits(float f) {
    uint32_t u = __float_as_uint(f);
    return (u & 0x80000000u) ? u : (u ^ 0x7fffffffu);
}
__device__ __forceinline__ float undbits_pos(uint32_t d) {
    return __uint_as_float(d ^ 0x7fffffffu);   // valid for positive originals
}

// ---------------- K1: pairwise IoU>0.5 bitmask (fine-grained, 16-bit stores) ----------------
__global__ void __launch_bounds__(256) k_mask(const float4* __restrict__ boxes) {
    __shared__ float4 sj[256]; __shared__ float aj[256];
    __shared__ float4 si[16];  __shared__ float ai[16];
    const int b  = blockIdx.y;
    const int rt = blockIdx.x >> 2;
    const int ct = blockIdx.x & 3;
    const int tid = threadIdx.x;

    {
        float4 v = boxes[b * NN + ct * 256 + tid];
        float y1 = fminf(v.x, v.z), y2 = fmaxf(v.x, v.z);
        float x1 = fminf(v.y, v.w), x2 = fmaxf(v.y, v.w);
        sj[tid] = make_float4(y1, x1, y2, x2);
        aj[tid] = (y2 - y1) * (x2 - x1);
    }
    if (tid < 16) {
        float4 v = boxes[b * NN + rt * 16 + tid];
        float y1 = fminf(v.x, v.z), y2 = fmaxf(v.x, v.z);
        float x1 = fminf(v.y, v.w), x2 = fmaxf(v.y, v.w);
        si[tid] = make_float4(y1, x1, y2, x2);
        ai[tid] = (y2 - y1) * (x2 - x1);
    }
    __syncthreads();

    const int r    = tid >> 4;
    const int hw   = tid & 15;
    const int lane = tid & 31;
    float4 A = si[r];
    float  a = ai[r];
    uint32_t bits = 0;

    #pragma unroll
    for (int t = 0; t < 16; t++) {
        int c  = (t + lane) & 15;
        int jl = hw * 16 + c;
        float4 Bx = sj[jl];
        float  ab = aj[jl];
        float ih    = fmaxf(fminf(A.z, Bx.z) - fmaxf(A.x, Bx.x), 0.0f);
        float iw2   = fmaxf(fminf(A.w, Bx.w) - fmaxf(A.y, Bx.y), 0.0f);
        float inter = ih * iw2;
        float uni   = fmaxf(a + ab - inter, 1e-12f);
        if ((inter + inter) - uni > uni * 0x1p-24f) bits |= (1u << c);
    }
    uint16_t* gm16 = reinterpret_cast<uint16_t*>(g_mask);
    gm16[(size_t)(b * NN + rt * 16 + r) * 64 + ct * 16 + hw] = (uint16_t)bits;
}

// ---------------- K2: chunked bucket-select + hybrid sort + ballot greedy (256 thr) ----------------
__global__ void __launch_bounds__(256) k_nms(const float* __restrict__ scores) {
    __shared__ uint32_t hist[1025];
    __shared__ uint32_t chkey[CHNK];
    __shared__ uint16_t chidx[CHNK];
    __shared__ alignas(16) uint32_t rows[CHNK * 32];   // 32KB (fallback reuses as u64 keys)
    __shared__ float    kept_s[KPC];
    __shared__ int      kept_i[KPC];
    __shared__ uint32_t wsum[8];
    __shared__ int      s_cnt, s_bhi, s_kc, s_done, s_fb;

    const int c    = blockIdx.x;
    const int b    = blockIdx.y;
    const int tid  = threadIdx.x;
    const int lane = tid & 31;
    const uint32_t BASE = 0x80F;             // dbits(1.0f) >> 19

    #pragma unroll
    for (int k = 0; k < 4; k++) hist[tid * 4 + k] = 0;
    if (tid == 0) { hist[1024] = 0; s_kc = 0; s_done = 0; s_fb = 0; }

    uint32_t key[4], binv[4]; bool val[4];
    #pragma unroll
    for (int k = 0; k < 4; k++) {
        int i = tid + k * 256;
        float s = scores[(b * NN + i) * CC + c];
        val[k] = (s > STHR);
        key[k] = dbits(s);
        int raw = (int)(key[k] >> 19) - (int)BASE;
        binv[k] = (uint32_t)min(max(raw, 0), 1023);
    }
    __syncthreads();
    #pragma unroll
    for (int k = 0; k < 4; k++) if (val[k]) atomicAdd(&hist[binv[k]], 1u);
    __syncthreads();

    // exclusive scan of 1024 bins (4 bins/thread, 8 warps)
    {
        uint32_t h[4];
        #pragma unroll
        for (int k = 0; k < 4; k++) h[k] = hist[4 * tid + k];
        uint32_t s4 = h[0] + h[1] + h[2] + h[3];
        uint32_t inc = s4;
        #pragma unroll
        for (int o = 1; o < 32; o <<= 1) {
            uint32_t v = __shfl_up_sync(0xffffffffu, inc, o);
            if ((tid & 31) >= o) inc += v;
        }
        if ((tid & 31) == 31) wsum[tid >> 5] = inc;
        __syncthreads();
        if (tid < 8) {
            uint32_t v = wsum[tid], in2 = v;
            #pragma unroll
            for (int o = 1; o < 8; o <<= 1) {
                uint32_t x = __shfl_up_sync(0x000000ffu, in2, o);
                if (tid >= o) in2 += x;
            }
            wsum[tid] = in2 - v;
        }
        __syncthreads();
        uint32_t excl = wsum[tid >> 5] + (inc - s4);
        uint32_t c1 = excl + h[0], c2 = c1 + h[1], c3 = c2 + h[2], c4 = excl + s4;
        hist[4 * tid] = excl; hist[4 * tid + 1] = c1; hist[4 * tid + 2] = c2; hist[4 * tid + 3] = c3;
        if (tid == 255) hist[1024] = c4;
    }
    __syncthreads();

    const int total = (int)hist[1024];
    uint32_t sup = 0;    // persistent suppressed bitmap (warp0, lane w = word w)
    int      kc  = 0;    // persistent kept count (warp0)
    int binLo = 0;

    for (int chunk = 0; chunk < 8; chunk++) {
        if (s_kc >= KPC || s_done >= total) break;

        if (tid == 0) { s_bhi = binLo; s_cnt = 0; }
        __syncthreads();
        const uint32_t base = hist[binLo];
        #pragma unroll
        for (int k = 1; k <= 4; k++) {
            int e = 4 * tid + k;
            if (hist[e] - base <= (uint32_t)CHNK) atomicMax(&s_bhi, e);
        }
        __syncthreads();
        const int binHi = s_bhi;
        if (binHi == binLo) { if (tid == 0) s_fb = 1; __syncthreads(); break; }
        const int P = (int)(hist[binHi] - base);

        // compact chunk members
        #pragma unroll
        for (int k = 0; k < 4; k++) {
            if (val[k] && binv[k] >= (uint32_t)binLo && binv[k] < (uint32_t)binHi) {
                int pos = atomicAdd(&s_cnt, 1);
                chkey[pos] = key[k];
                chidx[pos] = (uint16_t)(tid + k * 256);
            }
        }
        __syncthreads();
        if (tid >= P) { chkey[tid] = 0xFFFFFFFFu; chidx[tid] = 0xFFFF; }
        __syncthreads();

        if (P > 0) {
            // hybrid bitonic sort 256: (key,idx) ascending; intra-warp via shfl
            uint32_t mk = chkey[tid], mi = chidx[tid];
            for (int k2 = 2; k2 <= CHNK; k2 <<= 1) {
                for (int j = k2 >> 1; j > 0; j >>= 1) {
                    if (j >= 32) {
                        __syncthreads();
                        chkey[tid] = mk; chidx[tid] = (uint16_t)mi;
                        __syncthreads();
                        int p2 = tid ^ j;
                        uint32_t pk = chkey[p2], pi = chidx[p2];
                        bool up = ((tid & k2) == 0);
                        bool keep_min = (((tid & j) == 0) == up);
                        bool plt = (pk < mk) || (pk == mk && pi < mi);
                        if (keep_min == plt) { mk = pk; mi = pi; }
                    } else {
                        uint32_t pk = __shfl_xor_sync(0xffffffffu, mk, j);
                        uint32_t pi = __shfl_xor_sync(0xffffffffu, mi, j);
                        bool up = ((tid & k2) == 0);
                        bool keep_min = (((tid & j) == 0) == up);
                        bool plt = (pk < mk) || (pk == mk && pi < mi);
                        if (keep_min == plt) { mk = pk; mi = pi; }
                    }
                }
            }
            __syncthreads();
            chkey[tid] = mk; chidx[tid] = (uint16_t)mi;
            __syncthreads();

            // preload chunk mask rows (vectorized, 8 uint4/thread)
            {
                const uint4* gm4 = reinterpret_cast<const uint4*>(g_mask);
                uint4* rw4 = reinterpret_cast<uint4*>(rows);
                for (int l = tid; l < P * 8; l += 256) {
                    int r = l >> 3, q = l & 7;
                    int o = (int)chidx[r];
                    rw4[(r << 3) | q] = gm4[(b * NN + o) * 8 + q];
                }
            }
            __syncthreads();

            // group-of-32 parallel greedy on warp 0
            if (tid < 32) {
                const uint32_t lowmask = (lane == 0) ? 0u : (0xffffffffu >> (32 - lane));
                for (int g0 = 0; g0 < P && kc < KPC; g0 += 32) {
                    int l = g0 + lane;
                    bool has = (l < P);
                    uint32_t o = 0, keyv = 0xFFFFFFFFu;
                    if (has) { o = chidx[l]; keyv = chkey[l]; }
                    uint32_t wl2 = o >> 5, bl = o & 31;

                    uint32_t wsup = __shfl_sync(0xffffffffu, sup, (int)wl2);
                    bool alive0 = has && !((wsup >> bl) & 1u);

                    uint32_t colbits = 0;
                    int gcnt = min(32, P - g0);
                    for (int m = 0; m < gcnt; m++) {
                        uint32_t rm = rows[((g0 + m) << 5) + wl2];
                        colbits |= ((rm >> bl) & 1u) << m;
                    }

                    uint32_t alive_mask = __ballot_sync(0xffffffffu, alive0);
                    #pragma unroll 4
                    for (int it = 0; it < 32; it++) {
                        bool a = alive0 && ((alive_mask & colbits & lowmask) == 0);
                        uint32_t nm = __ballot_sync(0xffffffffu, a);
                        if (nm == alive_mask) break;
                        alive_mask = nm;
                    }

                    int navail = KPC - kc;
                    int myrank = __popc(alive_mask & lowmask);
                    bool keepme = ((alive_mask >> lane) & 1u) && (myrank < navail);
                    uint32_t kept_mask = __ballot_sync(0xffffffffu, keepme);
                    if (keepme) {
                        kept_i[kc + myrank] = (int)o;
                        kept_s[kc + myrank] = undbits_pos(keyv);
                    }
                    uint32_t km = kept_mask;
                    while (km) {
                        int m = __ffs(km) - 1; km &= km - 1;
                        sup |= rows[((g0 + m) << 5) + lane];
                    }
                    kc += __popc(kept_mask);
                }
                if (tid == 0) s_kc = kc;
            }
        }
        __syncthreads();
        if (tid == 0) s_done += P;
        binLo = binHi;
        __syncthreads();
    }
    __syncthreads();

    // fallback: degenerate distribution (never expected) -> full sort + sequential greedy
    if (s_fb || (s_kc < KPC && s_done < total)) {
        uint64_t* keys = reinterpret_cast<uint64_t*>(rows);
        #pragma unroll
        for (int k = 0; k < 4; k++) {
            int i = tid + k * 256;
            uint32_t kb = val[k] ? key[k] : 0xFFFFFFFFu;
            keys[i] = (((uint64_t)kb) << 32) | (uint32_t)i;
        }
        __syncthreads();
        for (int k2 = 2; k2 <= NN; k2 <<= 1) {
            for (int j = k2 >> 1; j > 0; j >>= 1) {
                #pragma unroll
                for (int t2 = 0; t2 < 4; t2++) {
                    int i2 = tid + t2 * 256, ixj = i2 ^ j;
                    if (ixj > i2) {
                        uint64_t a = keys[i2], d2 = keys[ixj];
                        bool up = ((i2 & k2) == 0);
                        if ((a > d2) == up) { keys[i2] = d2; keys[ixj] = a; }
                    }
                }
                __syncthreads();
            }
        }
        if (tid < 32) {
            uint32_t sup2 = 0; int kc2 = 0;
            for (int p = 0; p < NN; p++) {
                uint64_t kk = keys[p];
                if ((uint32_t)(kk >> 32) == 0xFFFFFFFFu) break;
                uint32_t o   = (uint32_t)kk & (NN - 1);
                uint32_t row = g_mask[(b * NN + o) * 32 + tid];
                uint32_t wv  = __shfl_sync(0xffffffffu, sup2, (int)(o >> 5));
                if (!((wv >> (o & 31)) & 1u)) {
                    if (tid == 0) { kept_i[kc2] = (int)o; kept_s[kc2] = undbits_pos((uint32_t)(kk >> 32)); }
                    sup2 |= row;
                    kc2++;
                    if (kc2 == KPC) break;
                }
            }
            if (tid == 0) s_kc = kc2;
        }
        __syncthreads();
    }

    const int kcf = s_kc;
    if (tid < KPC) {
        int slot = (b * CC + c) * KPC + tid;
        if (tid < kcf) { g_stage_s[slot] = kept_s[tid]; g_stage_b[slot] = kept_i[tid]; }
        else           { g_stage_s[slot] = NEGV;        g_stage_b[slot] = 0; }
    }
}

// ---------------- K3: per-image top-300 of 8000 + output ----------------
__global__ void __launch_bounds__(1024) k_final(const float* __restrict__ boxes,
                                                float* __restrict__ out) {
    __shared__ uint32_t hist[4097];
    __shared__ uint32_t fkey[FSEL];
    __shared__ uint16_t fidx[FSEL];
    __shared__ uint32_t wsum[32];
    __shared__ int      s_cnt, s_bsel, s_total, s_m;

    const int b   = blockIdx.x;
    const int tid = threadIdx.x;
    const int M   = CC * KPC;
    const uint32_t BASE13 = 0x203FF;

    #pragma unroll
    for (int k = 0; k < 4; k++) hist[tid * 4 + k] = 0;
    if (tid == 0) { hist[4096] = 0; s_cnt = 0; s_bsel = 0; }

    float vals[8]; int idxs[8]; uint32_t keyb[8]; uint32_t binb[8]; bool valb[8];
    #pragma unroll
    for (int k = 0; k < 8; k++) {
        int f = tid + k * 1024;
        float s = (f < M) ? g_stage_s[b * M + f] : NEGV;
        vals[k] = s; idxs[k] = (f < M) ? f : 0;
        valb[k] = (s > NEGV * 0.5f);
        keyb[k] = dbits(s);
        int raw = (int)(keyb[k] >> 13) - (int)BASE13;
        binb[k] = (uint32_t)min(max(raw, 0), 4095);
    }
    __syncthreads();
    #pragma unroll
    for (int k = 0; k < 8; k++) if (valb[k]) atomicAdd(&hist[binb[k]], 1u);
    __syncthreads();

    uint32_t h[4];
    #pragma unroll
    for (int k = 0; k < 4; k++) h[k] = hist[4 * tid + k];
    uint32_t s4 = h[0] + h[1] + h[2] + h[3];
    uint32_t inc = s4;
    #pragma unroll
    for (int o = 1; o < 32; o <<= 1) {
        uint32_t v = __shfl_up_sync(0xffffffffu, inc, o);
        if ((tid & 31) >= o) inc += v;
    }
    if ((tid & 31) == 31) wsum[tid >> 5] = inc;
    __syncthreads();
    if (tid < 32) {
        uint32_t v = wsum[tid], in2 = v;
        #pragma unroll
        for (int o = 1; o < 32; o <<= 1) {
            uint32_t x = __shfl_up_sync(0xffffffffu, in2, o);
            if (tid >= o) in2 += x;
        }
        wsum[tid] = in2 - v;
    }
    __syncthreads();
    uint32_t excl = wsum[tid >> 5] + (inc - s4);
    uint32_t cum1 = excl + h[0], cum2 = cum1 + h[1], cum3 = cum2 + h[2], cum4 = excl + s4;
    hist[4 * tid] = excl; hist[4 * tid + 1] = cum1; hist[4 * tid + 2] = cum2; hist[4 * tid + 3] = cum3;
    if (tid == 1023) hist[4096] = cum4;
    if (cum1 <= (uint32_t)FSEL) atomicMax(&s_bsel, 4 * tid + 1);
    if (cum2 <= (uint32_t)FSEL) atomicMax(&s_bsel, 4 * tid + 2);
    if (cum3 <= (uint32_t)FSEL) atomicMax(&s_bsel, 4 * tid + 3);
    if (cum4 <= (uint32_t)FSEL) atomicMax(&s_bsel, 4 * tid + 4);
    __syncthreads();

    const int Bsel  = s_bsel;
    int P           = (int)hist[Bsel];
    const int total = (int)hist[4096];

    if (P >= MAXT || P >= total) {
        #pragma unroll
        for (int k = 0; k < 8; k++) {
            if (valb[k] && binb[k] < (uint32_t)Bsel) {
                int pos = atomicAdd(&s_cnt, 1);
                if (pos < FSEL) { fkey[pos] = keyb[k]; fidx[pos] = (uint16_t)idxs[k]; }
            }
        }
        if (tid == 0) s_m = P;
    } else {
        float lo = 0.0f, hi2 = 1.0f;
        for (int it = 0; it < 30; it++) {
            float mid = 0.5f * (lo + hi2);
            int cnt = 0;
            #pragma unroll
            for (int k = 0; k < 8; k++) cnt += (vals[k] > mid);
            #pragma unroll
            for (int o = 16; o; o >>= 1) cnt += __shfl_down_sync(0xffffffffu, cnt, o);
            if ((tid & 31) == 0) wsum[tid >> 5] = (uint32_t)cnt;
            __syncthreads();
            if (tid == 0) {
                int tot = 0;
                #pragma unroll
                for (int w2 = 0; w2 < 32; w2++) tot += (int)wsum[w2];
                s_total = tot;
            }
            __syncthreads();
            if (s_total >= MAXT) lo = mid; else hi2 = mid;
            __syncthreads();
        }
        if (tid == 0) s_cnt = 0;
        __syncthreads();
        #pragma unroll
        for (int k = 0; k < 8; k++) {
            if (vals[k] > lo) {
                int pos = atomicAdd(&s_cnt, 1);
                if (pos < FSEL) { fkey[pos] = dbits(vals[k]); fidx[pos] = (uint16_t)idxs[k]; }
            }
        }
        __syncthreads();
        if (tid == 0) s_m = min(s_cnt, FSEL);
    }
    __syncthreads();
    const int m = s_m;
    if (tid < FSEL && tid >= m) { fkey[tid] = 0xFFFFFFFFu; fidx[tid] = 0xFFFF; }
    __syncthreads();

    {
        uint32_t mk = 0xFFFFFFFFu, mi = 0xFFFFu;
        if (tid < FSEL) { mk = fkey[tid]; mi = fidx[tid]; }
        for (int k2 = 2; k2 <= FSEL; k2 <<= 1) {
            for (int j = k2 >> 1; j > 0; j >>= 1) {
                if (j >= 32) {
                    __syncthreads();
                    if (tid < FSEL) { fkey[tid] = mk; fidx[tid] = (uint16_t)mi; }
                    __syncthreads();
                    if (tid < FSEL) {
                        int p2 = tid ^ j;
                        uint32_t pk = fkey[p2], pi = fidx[p2];
                        bool up = ((tid & k2) == 0);
                        bool keep_min = (((tid & j) == 0) == up);
                        bool plt = (pk < mk) || (pk == mk && pi < mi);
                        if (keep_min == plt) { mk = pk; mi = pi; }
                    }
                } else if (tid < FSEL) {
                    uint32_t pk = __shfl_xor_sync(0xffffffffu, mk, j);
                    uint32_t pi = __shfl_xor_sync(0xffffffffu, mi, j);
                    bool up = ((tid & k2) == 0);
                    bool keep_min = (((tid & j) == 0) == up);
                    bool plt = (pk < mk) || (pk == mk && pi < mi);
                    if (keep_min == plt) { mk = pk; mi = pi; }
                }
            }
        }
        __syncthreads();
        if (tid < FSEL) { fkey[tid] = mk; fidx[tid] = (uint16_t)mi; }
        __syncthreads();
    }

    if (tid < MAXT) {
        bool valid = (tid < m);
        float sc = 0.0f, cls = 0.0f, bx0 = 0.0f, bx1 = 0.0f, bx2 = 0.0f, bx3 = 0.0f;
        if (valid) {
            int f = (int)fidx[tid];
            sc  = g_stage_s[b * M + f];
            cls = (float)(f / KPC);
            int bidx = g_stage_b[b * M + f];
            float4 bv = reinterpret_cast<const float4*>(boxes)[b * NN + bidx];
            bx0 = fminf(fmaxf(bv.x, 0.0f), 1.0f);
            bx1 = fminf(fmaxf(bv.y, 0.0f), 1.0f);
            bx2 = fminf(fmaxf(bv.z, 0.0f), 1.0f);
            bx3 = fminf(fmaxf(bv.w, 0.0f), 1.0f);
        }
        out[b * MAXT + tid] = sc;
        float* ob = out + BB * MAXT + (b * MAXT + tid) * 4;
        ob[0] = bx0; ob[1] = bx1; ob[2] = bx2; ob[3] = bx3;
        out[BB * MAXT * 5 + b * MAXT + tid] = cls;
    }
    if (tid == 0) out[BB * MAXT * 6 + b] = (float)min(m, MAXT);
}

// ---------------- launch ----------------
extern "C" void kernel_launch(void* const* d_in, const int* in_sizes, int n_in,
                              void* d_out, int out_size) {
    const float* scores = (const float*)d_in[0];   // [4,1024,80] f32
    const float* boxes  = (const float*)d_in[1];   // [4,1024,1,4] f32
    float* out = (float*)d_out;

    k_mask<<<dim3(256, BB), 256>>>((const float4*)boxes);
    k_nms<<<dim3(CC, BB), 256>>>(scores);
    k_final<<<BB, 1024>>>(boxes, out);
}

// round 10
// speedup vs baseline: 1.6237x; 1.0616x over previous
#include <cuda_runtime.h>
#include <stdint.h>

#define BB   4
#define NN   1024
#define CC   80
#define KPC  100
#define MAXT 300
#define NEGV (-1e30f)
#define STHR 0.001f
#define CHNK 256     // k_nms chunk capacity
#define FSEL 512     // k_final selection cap

// ---------------- scratch ----------------
__device__ uint32_t g_mask[BB * NN * 32];
__device__ float    g_stage_s[BB * CC * KPC];
__device__ int      g_stage_b[BB * CC * KPC];

__device__ __forceinline__ uint32_t dbits(float f) {
    uint32_t u = __float_as_uint(f);
    return (u & 0x80000000u) ? u : (u ^ 0x7fffffffu);
}
__device__ __forceinline__ float undbits_pos(uint32_t d) {
    return __uint_as_float(d ^ 0x7fffffffu);   // valid for positive originals
}

// ---------------- K1: pairwise IoU>0.5 bitmask (fine-grained, 16-bit stores) ----------------
__global__ void __launch_bounds__(256) k_mask(const float4* __restrict__ boxes) {
    __shared__ float4 sj[256]; __shared__ float aj[256];
    __shared__ float4 si[16];  __shared__ float ai[16];
    const int b  = blockIdx.y;
    const int rt = blockIdx.x >> 2;
    const int ct = blockIdx.x & 3;
    const int tid = threadIdx.x;

    {
        float4 v = boxes[b * NN + ct * 256 + tid];
        float y1 = fminf(v.x, v.z), y2 = fmaxf(v.x, v.z);
        float x1 = fminf(v.y, v.w), x2 = fmaxf(v.y, v.w);
        sj[tid] = make_float4(y1, x1, y2, x2);
        aj[tid] = (y2 - y1) * (x2 - x1);
    }
    if (tid < 16) {
        float4 v = boxes[b * NN + rt * 16 + tid];
        float y1 = fminf(v.x, v.z), y2 = fmaxf(v.x, v.z);
        float x1 = fminf(v.y, v.w), x2 = fmaxf(v.y, v.w);
        si[tid] = make_float4(y1, x1, y2, x2);
        ai[tid] = (y2 - y1) * (x2 - x1);
    }
    __syncthreads();

    const int r    = tid >> 4;
    const int hw   = tid & 15;
    const int lane = tid & 31;
    float4 A = si[r];
    float  a = ai[r];
    uint32_t bits = 0;

    #pragma unroll
    for (int t = 0; t < 16; t++) {
        int c  = (t + lane) & 15;
        int jl = hw * 16 + c;
        float4 Bx = sj[jl];
        float  ab = aj[jl];
        float ih    = fmaxf(fminf(A.z, Bx.z) - fmaxf(A.x, Bx.x), 0.0f);
        float iw2   = fmaxf(fminf(A.w, Bx.w) - fmaxf(A.y, Bx.y), 0.0f);
        float inter = ih * iw2;
        float uni   = fmaxf(a + ab - inter, 1e-12f);
        if ((inter + inter) - uni > uni * 0x1p-24f) bits |= (1u << c);
    }
    uint16_t* gm16 = reinterpret_cast<uint16_t*>(g_mask);
    gm16[(size_t)(b * NN + rt * 16 + r) * 64 + ct * 16 + hw] = (uint16_t)bits;
}

// ---------------- K2: chunked bucket-select + alive filter + hybrid sort + ballot greedy ----------------
__global__ void __launch_bounds__(256) k_nms(const float* __restrict__ scores) {
    __shared__ uint32_t hist[1025];
    __shared__ uint32_t chkey[CHNK];
    __shared__ uint16_t chidx[CHNK];
    __shared__ alignas(16) uint32_t rows[CHNK * 32];   // 32KB (fallback reuses as u64 keys)
    __shared__ uint32_t sup_sh[32];                    // mirror of warp0's sup bitmap
    __shared__ float    kept_s[KPC];
    __shared__ int      kept_i[KPC];
    __shared__ uint32_t wsum[8];
    __shared__ int      s_cnt, s_bhi, s_kc, s_done, s_fb;

    const int c    = blockIdx.x;
    const int b    = blockIdx.y;
    const int tid  = threadIdx.x;
    const int lane = tid & 31;
    const uint32_t BASE = 0x80F;             // dbits(1.0f) >> 19

    #pragma unroll
    for (int k = 0; k < 4; k++) hist[tid * 4 + k] = 0;
    if (tid < 32) sup_sh[tid] = 0;
    if (tid == 0) { hist[1024] = 0; s_kc = 0; s_done = 0; s_fb = 0; }

    uint32_t key[4], binv[4]; bool val[4];
    #pragma unroll
    for (int k = 0; k < 4; k++) {
        int i = tid + k * 256;
        float s = scores[(b * NN + i) * CC + c];
        val[k] = (s > STHR);
        key[k] = dbits(s);
        int raw = (int)(key[k] >> 19) - (int)BASE;
        binv[k] = (uint32_t)min(max(raw, 0), 1023);
    }
    __syncthreads();
    #pragma unroll
    for (int k = 0; k < 4; k++) if (val[k]) atomicAdd(&hist[binv[k]], 1u);
    __syncthreads();

    // exclusive scan of 1024 bins (4 bins/thread, 8 warps)
    {
        uint32_t h[4];
        #pragma unroll
        for (int k = 0; k < 4; k++) h[k] = hist[4 * tid + k];
        uint32_t s4 = h[0] + h[1] + h[2] + h[3];
        uint32_t inc = s4;
        #pragma unroll
        for (int o = 1; o < 32; o <<= 1) {
            uint32_t v = __shfl_up_sync(0xffffffffu, inc, o);
            if ((tid & 31) >= o) inc += v;
        }
        if ((tid & 31) == 31) wsum[tid >> 5] = inc;
        __syncthreads();
        if (tid < 8) {
            uint32_t v = wsum[tid], in2 = v;
            #pragma unroll
            for (int o = 1; o < 8; o <<= 1) {
                uint32_t x = __shfl_up_sync(0x000000ffu, in2, o);
                if (tid >= o) in2 += x;
            }
            wsum[tid] = in2 - v;
        }
        __syncthreads();
        uint32_t excl = wsum[tid >> 5] + (inc - s4);
        uint32_t c1 = excl + h[0], c2 = c1 + h[1], c3 = c2 + h[2], c4 = excl + s4;
        hist[4 * tid] = excl; hist[4 * tid + 1] = c1; hist[4 * tid + 2] = c2; hist[4 * tid + 3] = c3;
        if (tid == 255) hist[1024] = c4;
    }
    __syncthreads();

    const int total = (int)hist[1024];
    uint32_t sup = 0;    // persistent suppressed bitmap (warp0, lane w = word w)
    int      kc  = 0;    // persistent kept count (warp0)
    int binLo = 0;

    for (int chunk = 0; chunk < 8; chunk++) {
        if (s_kc >= KPC || s_done >= total) break;

        if (tid == 0) { s_bhi = binLo; s_cnt = 0; }
        __syncthreads();
        const uint32_t base = hist[binLo];
        #pragma unroll
        for (int k = 1; k <= 4; k++) {
            int e = 4 * tid + k;
            if (hist[e] - base <= (uint32_t)CHNK) atomicMax(&s_bhi, e);
        }
        __syncthreads();
        const int binHi = s_bhi;
        if (binHi == binLo) { if (tid == 0) s_fb = 1; __syncthreads(); break; }
        const int rangeCnt = (int)(hist[binHi] - base);   // unfiltered examined count

        // compact chunk members, dropping already-suppressed candidates (exact: monotone)
        #pragma unroll
        for (int k = 0; k < 4; k++) {
            int i = tid + k * 256;
            if (val[k] && binv[k] >= (uint32_t)binLo && binv[k] < (uint32_t)binHi &&
                !((sup_sh[i >> 5] >> (i & 31)) & 1u)) {
                int pos = atomicAdd(&s_cnt, 1);
                chkey[pos] = key[k];
                chidx[pos] = (uint16_t)i;
            }
        }
        __syncthreads();
        const int P = s_cnt;
        if (tid >= P) { chkey[tid] = 0xFFFFFFFFu; chidx[tid] = 0xFFFF; }
        __syncthreads();

        if (P > 0) {
            // hybrid bitonic sort 256: (key,idx) ascending; intra-warp via shfl
            uint32_t mk = chkey[tid], mi = chidx[tid];
            for (int k2 = 2; k2 <= CHNK; k2 <<= 1) {
                for (int j = k2 >> 1; j > 0; j >>= 1) {
                    if (j >= 32) {
                        __syncthreads();
                        chkey[tid] = mk; chidx[tid] = (uint16_t)mi;
                        __syncthreads();
                        int p2 = tid ^ j;
                        uint32_t pk = chkey[p2], pi = chidx[p2];
                        bool up = ((tid & k2) == 0);
                        bool keep_min = (((tid & j) == 0) == up);
                        bool plt = (pk < mk) || (pk == mk && pi < mi);
                        if (keep_min == plt) { mk = pk; mi = pi; }
                    } else {
                        uint32_t pk = __shfl_xor_sync(0xffffffffu, mk, j);
                        uint32_t pi = __shfl_xor_sync(0xffffffffu, mi, j);
                        bool up = ((tid & k2) == 0);
                        bool keep_min = (((tid & j) == 0) == up);
                        bool plt = (pk < mk) || (pk == mk && pi < mi);
                        if (keep_min == plt) { mk = pk; mi = pi; }
                    }
                }
            }
            __syncthreads();
            chkey[tid] = mk; chidx[tid] = (uint16_t)mi;
            __syncthreads();

            // preload chunk mask rows (vectorized, alive candidates only)
            {
                const uint4* gm4 = reinterpret_cast<const uint4*>(g_mask);
                uint4* rw4 = reinterpret_cast<uint4*>(rows);
                for (int l = tid; l < P * 8; l += 256) {
                    int r = l >> 3, q = l & 7;
                    int o = (int)chidx[r];
                    rw4[(r << 3) | q] = gm4[(b * NN + o) * 8 + q];
                }
            }
            __syncthreads();

            // group-of-32 parallel greedy on warp 0
            if (tid < 32) {
                const uint32_t lowmask = (lane == 0) ? 0u : (0xffffffffu >> (32 - lane));
                for (int g0 = 0; g0 < P && kc < KPC; g0 += 32) {
                    int l = g0 + lane;
                    bool has = (l < P);
                    uint32_t o = 0, keyv = 0xFFFFFFFFu;
                    if (has) { o = chidx[l]; keyv = chkey[l]; }
                    uint32_t wl2 = o >> 5, bl = o & 31;

                    uint32_t wsup = __shfl_sync(0xffffffffu, sup, (int)wl2);
                    bool alive0 = has && !((wsup >> bl) & 1u);
                    uint32_t alive_mask = __ballot_sync(0xffffffffu, alive0);
                    if (alive_mask == 0) continue;     // whole group already suppressed

                    uint32_t colbits = 0;
                    int gcnt = min(32, P - g0);
                    for (int m = 0; m < gcnt; m++) {
                        uint32_t rm = rows[((g0 + m) << 5) + wl2];
                        colbits |= ((rm >> bl) & 1u) << m;
                    }

                    #pragma unroll 4
                    for (int it = 0; it < 32; it++) {
                        bool a = alive0 && ((alive_mask & colbits & lowmask) == 0);
                        uint32_t nm = __ballot_sync(0xffffffffu, a);
                        if (nm == alive_mask) break;
                        alive_mask = nm;
                    }

                    int navail = KPC - kc;
                    int myrank = __popc(alive_mask & lowmask);
                    bool keepme = ((alive_mask >> lane) & 1u) && (myrank < navail);
                    uint32_t kept_mask = __ballot_sync(0xffffffffu, keepme);
                    if (keepme) {
                        kept_i[kc + myrank] = (int)o;
                        kept_s[kc + myrank] = undbits_pos(keyv);
                    }
                    uint32_t km = kept_mask;
                    while (km) {
                        int m = __ffs(km) - 1; km &= km - 1;
                        sup |= rows[((g0 + m) << 5) + lane];
                    }
                    kc += __popc(kept_mask);
                }
                sup_sh[lane] = sup;                    // publish for next chunk's filter
                if (lane == 0) s_kc = kc;
            }
        }
        __syncthreads();
        if (tid == 0) s_done += rangeCnt;
        binLo = binHi;
        __syncthreads();
    }
    __syncthreads();

    // fallback: degenerate distribution (never expected) -> full sort + sequential greedy
    if (s_fb || (s_kc < KPC && s_done < total)) {
        uint64_t* keys = reinterpret_cast<uint64_t*>(rows);
        #pragma unroll
        for (int k = 0; k < 4; k++) {
            int i = tid + k * 256;
            uint32_t kb = val[k] ? key[k] : 0xFFFFFFFFu;
            keys[i] = (((uint64_t)kb) << 32) | (uint32_t)i;
        }
        __syncthreads();
        for (int k2 = 2; k2 <= NN; k2 <<= 1) {
            for (int j = k2 >> 1; j > 0; j >>= 1) {
                #pragma unroll
                for (int t2 = 0; t2 < 4; t2++) {
                    int i2 = tid + t2 * 256, ixj = i2 ^ j;
                    if (ixj > i2) {
                        uint64_t a = keys[i2], d2 = keys[ixj];
                        bool up = ((i2 & k2) == 0);
                        if ((a > d2) == up) { keys[i2] = d2; keys[ixj] = a; }
                    }
                }
                __syncthreads();
            }
        }
        if (tid < 32) {
            uint32_t sup2 = 0; int kc2 = 0;
            for (int p = 0; p < NN; p++) {
                uint64_t kk = keys[p];
                if ((uint32_t)(kk >> 32) == 0xFFFFFFFFu) break;
                uint32_t o   = (uint32_t)kk & (NN - 1);
                uint32_t row = g_mask[(b * NN + o) * 32 + tid];
                uint32_t wv  = __shfl_sync(0xffffffffu, sup2, (int)(o >> 5));
                if (!((wv >> (o & 31)) & 1u)) {
                    if (tid == 0) { kept_i[kc2] = (int)o; kept_s[kc2] = undbits_pos((uint32_t)(kk >> 32)); }
                    sup2 |= row;
                    kc2++;
                    if (kc2 == KPC) break;
                }
            }
            if (tid == 0) s_kc = kc2;
        }
        __syncthreads();
    }

    const int kcf = s_kc;
    if (tid < KPC) {
        int slot = (b * CC + c) * KPC + tid;
        if (tid < kcf) { g_stage_s[slot] = kept_s[tid]; g_stage_b[slot] = kept_i[tid]; }
        else           { g_stage_s[slot] = NEGV;        g_stage_b[slot] = 0; }
    }
}

// ---------------- K3: per-image top-300 of 8000 + output ----------------
__global__ void __launch_bounds__(1024) k_final(const float* __restrict__ boxes,
                                                float* __restrict__ out) {
    __shared__ uint32_t hist[4097];
    __shared__ uint32_t fkey[FSEL];
    __shared__ uint16_t fidx[FSEL];
    __shared__ uint32_t wsum[32];
    __shared__ int      s_cnt, s_bsel, s_total, s_m;

    const int b   = blockIdx.x;
    const int tid = threadIdx.x;
    const int M   = CC * KPC;
    const uint32_t BASE13 = 0x203FF;

    #pragma unroll
    for (int k = 0; k < 4; k++) hist[tid * 4 + k] = 0;
    if (tid == 0) { hist[4096] = 0; s_cnt = 0; s_bsel = 0; }

    float vals[8]; int idxs[8]; uint32_t keyb[8]; uint32_t binb[8]; bool valb[8];
    #pragma unroll
    for (int k = 0; k < 8; k++) {
        int f = tid + k * 1024;
        float s = (f < M) ? g_stage_s[b * M + f] : NEGV;
        vals[k] = s; idxs[k] = (f < M) ? f : 0;
        valb[k] = (s > NEGV * 0.5f);
        keyb[k] = dbits(s);
        int raw = (int)(keyb[k] >> 13) - (int)BASE13;
        binb[k] = (uint32_t)min(max(raw, 0), 4095);
    }
    __syncthreads();
    #pragma unroll
    for (int k = 0; k < 8; k++) if (valb[k]) atomicAdd(&hist[binb[k]], 1u);
    __syncthreads();

    uint32_t h[4];
    #pragma unroll
    for (int k = 0; k < 4; k++) h[k] = hist[4 * tid + k];
    uint32_t s4 = h[0] + h[1] + h[2] + h[3];
    uint32_t inc = s4;
    #pragma unroll
    for (int o = 1; o < 32; o <<= 1) {
        uint32_t v = __shfl_up_sync(0xffffffffu, inc, o);
        if ((tid & 31) >= o) inc += v;
    }
    if ((tid & 31) == 31) wsum[tid >> 5] = inc;
    __syncthreads();
    if (tid < 32) {
        uint32_t v = wsum[tid], in2 = v;
        #pragma unroll
        for (int o = 1; o < 32; o <<= 1) {
            uint32_t x = __shfl_up_sync(0xffffffffu, in2, o);
            if (tid >= o) in2 += x;
        }
        wsum[tid] = in2 - v;
    }
    __syncthreads();
    uint32_t excl = wsum[tid >> 5] + (inc - s4);
    uint32_t cum1 = excl + h[0], cum2 = cum1 + h[1], cum3 = cum2 + h[2], cum4 = excl + s4;
    hist[4 * tid] = excl; hist[4 * tid + 1] = cum1; hist[4 * tid + 2] = cum2; hist[4 * tid + 3] = cum3;
    if (tid == 1023) hist[4096] = cum4;
    if (cum1 <= (uint32_t)FSEL) atomicMax(&s_bsel, 4 * tid + 1);
    if (cum2 <= (uint32_t)FSEL) atomicMax(&s_bsel, 4 * tid + 2);
    if (cum3 <= (uint32_t)FSEL) atomicMax(&s_bsel, 4 * tid + 3);
    if (cum4 <= (uint32_t)FSEL) atomicMax(&s_bsel, 4 * tid + 4);
    __syncthreads();

    const int Bsel  = s_bsel;
    int P           = (int)hist[Bsel];
    const int total = (int)hist[4096];

    if (P >= MAXT || P >= total) {
        #pragma unroll
        for (int k = 0; k < 8; k++) {
            if (valb[k] && binb[k] < (uint32_t)Bsel) {
                int pos = atomicAdd(&s_cnt, 1);
                if (pos < FSEL) { fkey[pos] = keyb[k]; fidx[pos] = (uint16_t)idxs[k]; }
            }
        }
        if (tid == 0) s_m = P;
    } else {
        float lo = 0.0f, hi2 = 1.0f;
        for (int it = 0; it < 30; it++) {
            float mid = 0.5f * (lo + hi2);
            int cnt = 0;
            #pragma unroll
            for (int k = 0; k < 8; k++) cnt += (vals[k] > mid);
            #pragma unroll
            for (int o = 16; o; o >>= 1) cnt += __shfl_down_sync(0xffffffffu, cnt, o);
            if ((tid & 31) == 0) wsum[tid >> 5] = (uint32_t)cnt;
            __syncthreads();
            if (tid == 0) {
                int tot = 0;
                #pragma unroll
                for (int w2 = 0; w2 < 32; w2++) tot += (int)wsum[w2];
                s_total = tot;
            }
            __syncthreads();
            if (s_total >= MAXT) lo = mid; else hi2 = mid;
            __syncthreads();
        }
        if (tid == 0) s_cnt = 0;
        __syncthreads();
        #pragma unroll
        for (int k = 0; k < 8; k++) {
            if (vals[k] > lo) {
                int pos = atomicAdd(&s_cnt, 1);
                if (pos < FSEL) { fkey[pos] = dbits(vals[k]); fidx[pos] = (uint16_t)idxs[k]; }
            }
        }
        __syncthreads();
        if (tid == 0) s_m = min(s_cnt, FSEL);
    }
    __syncthreads();
    const int m = s_m;
    if (tid < FSEL && tid >= m) { fkey[tid] = 0xFFFFFFFFu; fidx[tid] = 0xFFFF; }
    __syncthreads();

    {
        uint32_t mk = 0xFFFFFFFFu, mi = 0xFFFFu;
        if (tid < FSEL) { mk = fkey[tid]; mi = fidx[tid]; }
        for (int k2 = 2; k2 <= FSEL; k2 <<= 1) {
            for (int j = k2 >> 1; j > 0; j >>= 1) {
                if (j >= 32) {
                    __syncthreads();
                    if (tid < FSEL) { fkey[tid] = mk; fidx[tid] = (uint16_t)mi; }
                    __syncthreads();
                    if (tid < FSEL) {
                        int p2 = tid ^ j;
                        uint32_t pk = fkey[p2], pi = fidx[p2];
                        bool up = ((tid & k2) == 0);
                        bool keep_min = (((tid & j) == 0) == up);
                        bool plt = (pk < mk) || (pk == mk && pi < mi);
                        if (keep_min == plt) { mk = pk; mi = pi; }
                    }
                } else if (tid < FSEL) {
                    uint32_t pk = __shfl_xor_sync(0xffffffffu, mk, j);
                    uint32_t pi = __shfl_xor_sync(0xffffffffu, mi, j);
                    bool up = ((tid & k2) == 0);
                    bool keep_min = (((tid & j) == 0) == up);
                    bool plt = (pk < mk) || (pk == mk && pi < mi);
                    if (keep_min == plt) { mk = pk; mi = pi; }
                }
            }
        }
        __syncthreads();
        if (tid < FSEL) { fkey[tid] = mk; fidx[tid] = (uint16_t)mi; }
        __syncthreads();
    }

    if (tid < MAXT) {
        bool valid = (tid < m);
        float sc = 0.0f, cls = 0.0f, bx0 = 0.0f, bx1 = 0.0f, bx2 = 0.0f, bx3 = 0.0f;
        if (valid) {
            int f = (int)fidx[tid];
            sc  = g_stage_s[b * M + f];
            cls = (float)(f / KPC);
            int bidx = g_stage_b[b * M + f];
            float4 bv = reinterpret_cast<const float4*>(boxes)[b * NN + bidx];
            bx0 = fminf(fmaxf(bv.x, 0.0f), 1.0f);
            bx1 = fminf(fmaxf(bv.y, 0.0f), 1.0f);
            bx2 = fminf(fmaxf(bv.z, 0.0f), 1.0f);
            bx3 = fminf(fmaxf(bv.w, 0.0f), 1.0f);
        }
        out[b * MAXT + tid] = sc;
        float* ob = out + BB * MAXT + (b * MAXT + tid) * 4;
        ob[0] = bx0; ob[1] = bx1; ob[2] = bx2; ob[3] = bx3;
        out[BB * MAXT * 5 + b * MAXT + tid] = cls;
    }
    if (tid == 0) out[BB * MAXT * 6 + b] = (float)min(m, MAXT);
}

// ---------------- launch ----------------
extern "C" void kernel_launch(void* const* d_in, const int* in_sizes, int n_in,
                              void* d_out, int out_size) {
    const float* scores = (const float*)d_in[0];   // [4,1024,80] f32
    const float* boxes  = (const float*)d_in[1];   // [4,1024,1,4] f32
    float* out = (float*)d_out;

    k_mask<<<dim3(256, BB), 256>>>((const float4*)boxes);
    k_nms<<<dim3(CC, BB), 256>>>(scores);
    k_final<<<BB, 1024>>>(boxes, out);
}